// round 1
// baseline (speedup 1.0000x reference)
#include <cuda_runtime.h>

#define TM   64     // rows per CTA tile
#define KC   82     // K-chunk of W_edge staged in smem (656 = 8*82)
#define NF   656    // feature (GEMM-K) dimension: 16 pos + 640 RBF
#define EC   128    // output columns
#define NTHR 256

// ---- f32x2 packed-FMA helpers (sm_103a) --------------------------------
__device__ __forceinline__ unsigned long long pack2(float x) {
    unsigned long long r; unsigned u = __float_as_uint(x);
    asm("mov.b64 %0, {%1,%1};" : "=l"(r) : "r"(u));
    return r;
}
__device__ __forceinline__ void ffma2(unsigned long long& d,
                                      unsigned long long a,
                                      unsigned long long b) {
    asm("fma.rn.f32x2 %0, %1, %2, %0;" : "+l"(d) : "l"(a), "l"(b));
}
__device__ __forceinline__ float lo2(unsigned long long v) {
    return __uint_as_float((unsigned)(v & 0xffffffffull));
}
__device__ __forceinline__ float hi2(unsigned long long v) {
    return __uint_as_float((unsigned)(v >> 32));
}

// smem layout (floats): feat[NF*TM] | Wc[KC*EC] | dist[TM*41] | smul[TM]
#define SMEM_FLOATS (NF*TM + KC*EC + TM*41 + TM)

__global__ __launch_bounds__(NTHR, 1)
void spf_kernel(const float* __restrict__ X,
                const int*   __restrict__ residue_idx,
                const int*   __restrict__ chain_labels,
                const int*   __restrict__ E_idx,
                const float* __restrict__ W_pos,
                const float* __restrict__ b_pos,
                const float* __restrict__ W_edge,
                const float* __restrict__ ln_gamma,
                const float* __restrict__ ln_beta,
                float*       __restrict__ out,
                int Kn, int A, int nrows, int write_eidx)
{
    extern __shared__ float smem[];
    float* feat = smem;                 // [kk][r] : NF x TM
    float* Wc   = feat + NF * TM;       // [kk][c] : KC x EC
    float* dist = Wc + KC * EC;         // [r][a]  : TM x 41 (padded, conflict-free)
    float* smul = dist + TM * 41;       // self-edge multiplier per row

    const int tid  = threadIdx.x;
    const int row0 = blockIdx.x * TM;

    // ---------------- Phase 1a: distances + positional features ----------
    {
        const int r  = tid >> 2;        // 0..63
        const int a1 = tid & 3;         // bb atom slot
        const int row = row0 + r;
        if (row < nrows) {
            const int i = row / Kn;
            const int j = E_idx[row];
            const int bbm[4] = {1, 0, 2, 3};
            const float* bx = X + ((size_t)i * A + bbm[a1]) * 3;
            const float b0 = bx[0], b1 = bx[1], b2 = bx[2];
            const float* sx = X + ((size_t)j * A + 4) * 3;
            #pragma unroll
            for (int a2 = 0; a2 < 10; a2++) {
                float dx = b0 - sx[a2*3+0];
                float dy = b1 - sx[a2*3+1];
                float dz = b2 - sx[a2*3+2];
                dist[r*41 + a1*10 + a2] = sqrtf(dx*dx + dy*dy + dz*dz + 1e-6f);
            }
            if (a1 == 0) {
                smul[r] = (j == i) ? 0.0f : 1.0f;
                int off  = residue_idx[i] - residue_idx[j];
                int same = (chain_labels[i] == chain_labels[j]);
                int dpos = same ? min(max(off + 32, 0), 64) : 65;
                #pragma unroll
                for (int c = 0; c < 16; c++)
                    feat[c*TM + r] = W_pos[dpos*16 + c] + b_pos[c];
                if (write_eidx)
                    out[(size_t)nrows * EC + row] = (float)j;
            }
        } else {
            #pragma unroll
            for (int a2 = 0; a2 < 10; a2++) dist[r*41 + a1*10 + a2] = 0.0f;
            if (a1 == 0) {
                smul[r] = 0.0f;
                #pragma unroll
                for (int c = 0; c < 16; c++) feat[c*TM + r] = 0.0f;
            }
        }
    }
    __syncthreads();

    // ---------------- Phase 1b: RBF features -----------------------------
    // idx = f*64 + r  ->  coalesced STS into feat[(16+f)*TM + r]
    for (int idx = tid; idx < TM * 640; idx += NTHR) {
        int rr = idx & 63;
        int f  = idx >> 6;              // 0..639 : (a1*10+a2)*16 + m
        float d  = dist[rr*41 + (f >> 4)];
        float mu = 2.0f + (float)(f & 15) * (20.0f / 15.0f);
        float t  = (d - mu) * 0.8f;     // 1/sigma = 1/1.25
        feat[(16 + f)*TM + rr] = smul[rr] * __expf(-t * t);
    }
    __syncthreads();

    // ---------------- Phase 2: GEMM (656 x 128), f32x2 packed ------------
    const int ty = tid >> 4;            // 0..15 -> 4 rows each
    const int tx = tid & 15;            // 0..15 -> 8 cols each
    unsigned long long acc[4][4];
    #pragma unroll
    for (int i = 0; i < 4; i++)
        #pragma unroll
        for (int j = 0; j < 4; j++) acc[i][j] = 0ull;

    for (int chunk = 0; chunk < NF; chunk += KC) {
        // stage W chunk: KC*EC floats, coalesced float4 copy
        {
            const float4* Wg  = (const float4*)(W_edge + (size_t)chunk * EC);
            float4*       Wc4 = (float4*)Wc;
            for (int idx = tid; idx < KC * EC / 4; idx += NTHR)
                Wc4[idx] = Wg[idx];
        }
        __syncthreads();

        #pragma unroll 2
        for (int kk = 0; kk < KC; kk++) {
            float4 f4 = *(const float4*)&feat[(chunk + kk)*TM + ty*4];
            unsigned long long p0 = pack2(f4.x), p1 = pack2(f4.y),
                               p2 = pack2(f4.z), p3 = pack2(f4.w);
            const ulonglong2* wr = (const ulonglong2*)&Wc[kk*EC + tx*8];
            ulonglong2 wA = wr[0], wB = wr[1];
            ffma2(acc[0][0], p0, wA.x); ffma2(acc[0][1], p0, wA.y);
            ffma2(acc[0][2], p0, wB.x); ffma2(acc[0][3], p0, wB.y);
            ffma2(acc[1][0], p1, wA.x); ffma2(acc[1][1], p1, wA.y);
            ffma2(acc[1][2], p1, wB.x); ffma2(acc[1][3], p1, wB.y);
            ffma2(acc[2][0], p2, wA.x); ffma2(acc[2][1], p2, wA.y);
            ffma2(acc[2][2], p2, wB.x); ffma2(acc[2][3], p2, wB.y);
            ffma2(acc[3][0], p3, wA.x); ffma2(acc[3][1], p3, wA.y);
            ffma2(acc[3][2], p3, wB.x); ffma2(acc[3][3], p3, wB.y);
        }
        __syncthreads();
    }

    // ---------------- Phase 3: LayerNorm + store --------------------------
    float g[8], bb[8];
    #pragma unroll
    for (int c = 0; c < 8; c++) {
        g[c]  = ln_gamma[tx*8 + c];
        bb[c] = ln_beta [tx*8 + c];
    }

    #pragma unroll
    for (int ri = 0; ri < 4; ri++) {
        float v[8];
        #pragma unroll
        for (int ci = 0; ci < 4; ci++) {
            v[2*ci]   = lo2(acc[ri][ci]);
            v[2*ci+1] = hi2(acc[ri][ci]);
        }
        float s = 0.0f;
        #pragma unroll
        for (int c = 0; c < 8; c++) s += v[c];
        #pragma unroll
        for (int o = 8; o >= 1; o >>= 1)
            s += __shfl_xor_sync(0xffffffffu, s, o, 16);
        float mean = s * (1.0f / 128.0f);

        float q = 0.0f;
        #pragma unroll
        for (int c = 0; c < 8; c++) { float d = v[c] - mean; q += d * d; }
        #pragma unroll
        for (int o = 8; o >= 1; o >>= 1)
            q += __shfl_xor_sync(0xffffffffu, q, o, 16);
        float rstd = rsqrtf(q * (1.0f / 128.0f) + 1e-5f);

        int row = row0 + ty*4 + ri;
        if (row < nrows) {
            float4 o0, o1;
            o0.x = (v[0]-mean)*rstd*g[0] + bb[0];
            o0.y = (v[1]-mean)*rstd*g[1] + bb[1];
            o0.z = (v[2]-mean)*rstd*g[2] + bb[2];
            o0.w = (v[3]-mean)*rstd*g[3] + bb[3];
            o1.x = (v[4]-mean)*rstd*g[4] + bb[4];
            o1.y = (v[5]-mean)*rstd*g[5] + bb[5];
            o1.z = (v[6]-mean)*rstd*g[6] + bb[6];
            o1.w = (v[7]-mean)*rstd*g[7] + bb[7];
            *(float4*)&out[(size_t)row*EC + tx*8    ] = o0;
            *(float4*)&out[(size_t)row*EC + tx*8 + 4] = o1;
        }
    }
}

extern "C" void kernel_launch(void* const* d_in, const int* in_sizes, int n_in,
                              void* d_out, int out_size)
{
    const float* X           = (const float*)d_in[0];
    const int*   residue_idx = (const int*)  d_in[1];
    const int*   chain_lab   = (const int*)  d_in[2];
    const int*   E_idx       = (const int*)  d_in[3];
    // d_in[4] = atom_mask (unused by reference)
    const float* W_pos       = (const float*)d_in[5];
    const float* b_pos       = (const float*)d_in[6];
    const float* W_edge      = (const float*)d_in[7];
    const float* ln_gamma    = (const float*)d_in[8];
    const float* ln_beta     = (const float*)d_in[9];
    float*       out         = (float*)d_out;

    const int BL    = in_sizes[1];            // B*L
    const int nrows = in_sizes[3];            // B*L*K
    const int Kn    = nrows / BL;             // K = 30
    const int A     = in_sizes[0] / (BL * 3); // 14
    const int write_eidx = (out_size >= nrows * (EC + 1)) ? 1 : 0;

    const int grid = (nrows + TM - 1) / TM;
    const size_t shb = (size_t)SMEM_FLOATS * sizeof(float);

    cudaFuncSetAttribute(spf_kernel,
                         cudaFuncAttributeMaxDynamicSharedMemorySize, (int)shb);

    spf_kernel<<<grid, NTHR, shb>>>(X, residue_idx, chain_lab, E_idx,
                                    W_pos, b_pos, W_edge, ln_gamma, ln_beta,
                                    out, Kn, A, nrows, write_eidx);
}